// round 1
// baseline (speedup 1.0000x reference)
#include <cuda_runtime.h>
#include <cstdint>

// ---------------------------------------------------------------------------
// CustomSimpleGRU: 2-layer GRU-variant, 512 sequential steps.
//   gates = [inp, h] @ W + b ; z = sigmoid(chunk0) ; n = tanh(chunk2)
//   h' = (1-z)*n + z*h          (reset gate chunk is dead code -> skipped)
// Final: out[b] = h1_last[b,:] @ Wfc + bfc
//
// Persistent-kernel design:
//   grid = 128 CTAs x 256 thr. CTA i owns hidden cols [8i, 8i+8) of BOTH
//   layers (computes z & n for them, applies the h update).
//   Per layer: K split across 8 warps; thread tile 8 rows x 8 outcols using
//   packed fp32x2 FMA (fma.rn.f32x2) -> 128 FMA/cyc/SM.
//   Inputs + weight slices staged via double-buffered cp.async.
//   Two lightweight global barriers per step (release flag + acquire spin).
// ---------------------------------------------------------------------------

typedef unsigned long long ull;

#define BATCH 128
#define HID   1024
#define SEQ   512
#define INDIM 128
#define KC    64        // k-chunk size
#define KP    68        // inp smem row pitch (floats), 16B-aligned, odd/4 for banks
#define NWARP 8

__device__ float    g_h0[2][BATCH][HID];
__device__ float    g_h1[2][BATCH][HID];
__device__ unsigned g_flags[128 * 32];   // one 128B-strided flag per CTA

struct SM {
    float inp[2][BATCH][KP];   // staged input chunk [k-major? no: row][k], 2 buffers
    float wgt[2][KC][16];      // staged W chunk: 8 z-cols then 8 n-cols
    float red[NWARP][BATCH][16]; // cross-warp partial-sum buffer
};

// ---------------- packed fp32x2 helpers ----------------
__device__ __forceinline__ ull rep2(float v) {
    ull r;
    asm("mov.b64 %0, {%1, %1};" : "=l"(r) : "f"(v));
    return r;
}
__device__ __forceinline__ void fma2(ull& d, ull a, ull b) {
    asm("fma.rn.f32x2 %0, %1, %2, %0;" : "+l"(d) : "l"(a), "l"(b));
}

// ---------------- cp.async helpers ----------------
__device__ __forceinline__ void cp16(void* dst, const void* src) {
    unsigned d = (unsigned)__cvta_generic_to_shared(dst);
    asm volatile("cp.async.cg.shared.global [%0], [%1], 16;" :: "r"(d), "l"(src));
}
__device__ __forceinline__ void cp_commit() { asm volatile("cp.async.commit_group;"); }
__device__ __forceinline__ void cp_wait0()  { asm volatile("cp.async.wait_group 0;"); }
__device__ __forceinline__ void cp_wait1()  { asm volatile("cp.async.wait_group 1;"); }

// ---------------- global barrier (sense = monotonically increasing gen) ----
__device__ __forceinline__ void gbar(unsigned& gen) {
    gen++;
    __syncthreads();                    // all CTA writes done
    if (threadIdx.x == 0) {
        asm volatile("st.release.gpu.global.u32 [%0], %1;"
                     :: "l"(&g_flags[blockIdx.x * 32]), "r"(gen) : "memory");
    }
    if (threadIdx.x < 128) {            // thread i watches CTA i's flag
        const unsigned* f = &g_flags[threadIdx.x * 32];
        unsigned v;
        while (true) {
            asm volatile("ld.acquire.gpu.global.u32 %0, [%1];" : "=r"(v) : "l"(f) : "memory");
            if (v >= gen) break;
            __nanosleep(32);
        }
    }
    __syncthreads();
}

// ---------------- chunk staging ----------------
__device__ __forceinline__ void stage_chunk(SM* s, int bb,
                                            const float* __restrict__ src, int rstride, int koff,
                                            const float* __restrict__ W, int kw, int cb) {
    const int tid = threadIdx.x;
    // inp: 128 rows x 64 floats  (2048 float4 copies, 8 per thread)
    #pragma unroll
    for (int it = 0; it < 8; it++) {
        int idx = it * 256 + tid;
        int r = idx >> 4, q = idx & 15;
        cp16(&s->inp[bb][r][q * 4], src + (size_t)r * rstride + koff + q * 4);
    }
    // weights: 64 k x 16 cols (z cols cb..cb+7, n cols 2048+cb..+7)
    {
        int kk = tid >> 2, seg = tid & 3;
        int col = (seg < 2) ? (cb + seg * 4) : (2048 + cb + (seg - 2) * 4);
        cp16(&s->wgt[bb][kk][seg * 4], W + (size_t)(kw + kk) * 3072 + col);
    }
}

// ---------------- one GRU layer step for this CTA's 8 columns ----------------
__device__ __forceinline__ void run_layer(SM* s,
        const float* __restrict__ srcA, int strideA, int nA,
        const float* __restrict__ srcB, int strideB, int nB,
        const float* __restrict__ W, const float* __restrict__ bias,
        const float* __restrict__ hprev, float* __restrict__ hnext, int cb) {
    const int n    = nA + nB;
    const int tid  = threadIdx.x;
    const int w    = tid >> 5;
    const int lane = tid & 31;
    const int rg   = lane & 15;    // row group: rows rg + 16*j
    const int ch   = lane >> 4;    // 0 -> z cols, 1 -> n cols

    ull acc[8][4];
    #pragma unroll
    for (int j = 0; j < 8; j++)
        #pragma unroll
        for (int cp = 0; cp < 4; cp++) acc[j][cp] = 0ull;

    // prologue: stage chunk 0
    stage_chunk(s, 0, srcA, strideA, 0, W, 0, cb);
    cp_commit();

    for (int c = 0; c < n; c++) {
        const int bb = c & 1;
        if (c + 1 < n) {
            const float* p; int st, ko;
            if (c + 1 < nA) { p = srcA; st = strideA; ko = (c + 1) * KC; }
            else            { p = srcB; st = strideB; ko = (c + 1 - nA) * KC; }
            stage_chunk(s, (c + 1) & 1, p, st, ko, W, (c + 1) * KC, cb);
            cp_commit();
            cp_wait1();
        } else {
            cp_wait0();
        }
        __syncthreads();   // chunk c visible to all

        // warp w handles k-local [w*8, w*8+8)
        #pragma unroll
        for (int kk = 0; kk < 8; kk++) {
            const int k = w * 8 + kk;
            const ull* wrow = (const ull*)&s->wgt[bb][k][ch * 8];
            ull w0 = wrow[0], w1 = wrow[1], w2 = wrow[2], w3 = wrow[3];
            #pragma unroll
            for (int j = 0; j < 8; j++) {
                ull iv = rep2(s->inp[bb][rg + 16 * j][k]);
                fma2(acc[j][0], iv, w0);
                fma2(acc[j][1], iv, w1);
                fma2(acc[j][2], iv, w2);
                fma2(acc[j][3], iv, w3);
            }
        }
        __syncthreads();   // done with buffer bb before it is restaged
    }

    // cross-warp reduction: dump partials to shared
    #pragma unroll
    for (int j = 0; j < 8; j++)
        #pragma unroll
        for (int cp = 0; cp < 4; cp++)
            *(ull*)&s->red[w][rg + 16 * j][ch * 8 + 2 * cp] = acc[j][cp];
    __syncthreads();

    // reduce + activation + h update (each thread: 4 (row,col) cells)
    #pragma unroll
    for (int u0 = 0; u0 < 4; u0++) {
        int u   = u0 * 256 + tid;
        int row = u & 127;
        int hco = u >> 7;           // 0..7
        float z  = bias[cb + hco];
        float nn = bias[2048 + cb + hco];
        #pragma unroll
        for (int ww = 0; ww < NWARP; ww++) {
            z  += s->red[ww][row][hco];
            nn += s->red[ww][row][8 + hco];
        }
        z  = 1.0f / (1.0f + __expf(-z));
        nn = tanhf(nn);
        float hp = hprev[row * HID + cb + hco];
        hnext[row * HID + cb + hco] = (1.0f - z) * nn + z * hp;
    }
    __syncthreads();  // red free for next use
}

// ---------------- persistent kernel ----------------
__global__ void __launch_bounds__(256, 1)
gru_persistent(const float* __restrict__ x,
               const float* __restrict__ W0, const float* __restrict__ b0,
               const float* __restrict__ W1, const float* __restrict__ b1,
               const float* __restrict__ Wfc, const float* __restrict__ bfc,
               float* __restrict__ out) {
    extern __shared__ __align__(16) char sraw[];
    SM* s = (SM*)sraw;
    const int cb = blockIdx.x * 8;
    unsigned gen = 0;
    int p = 0;

    for (int t = 0; t < SEQ; t++) {
        const float* xt = x + (size_t)t * INDIM;   // x[b][t][k]: row stride SEQ*INDIM
        // layer 0: inp = [x_t (128), h0 (1024)], K = 1152 (18 chunks)
        run_layer(s, xt, SEQ * INDIM, 2,
                     &g_h0[p][0][0], HID, 16,
                     W0, b0, &g_h0[p][0][0], &g_h0[p ^ 1][0][0], cb);
        gbar(gen);
        // layer 1: inp = [h0_new (1024), h1 (1024)], K = 2048 (32 chunks)
        run_layer(s, &g_h0[p ^ 1][0][0], HID, 16,
                     &g_h1[p][0][0], HID, 16,
                     W1, b1, &g_h1[p][0][0], &g_h1[p ^ 1][0][0], cb);
        gbar(gen);
        p ^= 1;
    }

    // final FC: out[b] = h1_last[b,:] @ Wfc + bfc  (CTA b handles row b)
    const float* hf = &g_h1[p][0][0];
    const int row = blockIdx.x;
    float part = 0.0f;
    for (int j = threadIdx.x; j < HID; j += 256)
        part += hf[row * HID + j] * Wfc[j];
    float* rb = &s->red[0][0][0];
    rb[threadIdx.x] = part;
    __syncthreads();
    if (threadIdx.x == 0) {
        float tot = 0.0f;
        #pragma unroll 8
        for (int i = 0; i < 256; i++) tot += rb[i];
        out[row] = tot + bfc[0];
    }
}

// ---------------- per-launch state reset ----------------
__global__ void gru_init() {
    int i      = blockIdx.x * blockDim.x + threadIdx.x;
    int stride = gridDim.x * blockDim.x;
    for (int idx = i; idx < 2 * BATCH * HID; idx += stride) {
        ((float*)g_h0)[idx] = 0.0f;
        ((float*)g_h1)[idx] = 0.0f;
    }
    if (i < 128 * 32) g_flags[i] = 0u;
}

extern "C" void kernel_launch(void* const* d_in, const int* in_sizes, int n_in,
                              void* d_out, int out_size) {
    const float* x   = (const float*)d_in[0];
    const float* W0  = (const float*)d_in[1];
    const float* b0  = (const float*)d_in[2];
    const float* W1  = (const float*)d_in[3];
    const float* b1  = (const float*)d_in[4];
    const float* Wfc = (const float*)d_in[5];
    const float* bfc = (const float*)d_in[6];
    float* out = (float*)d_out;

    cudaFuncSetAttribute(gru_persistent,
                         cudaFuncAttributeMaxDynamicSharedMemorySize,
                         (int)sizeof(SM));
    gru_init<<<256, 256>>>();
    gru_persistent<<<128, 256, sizeof(SM)>>>(x, W0, b0, W1, b1, Wfc, bfc, out);
}

// round 4
// speedup vs baseline: 1.1643x; 1.1643x over previous
#include <cuda_runtime.h>
#include <cstdint>

// ---------------------------------------------------------------------------
// CustomSimpleGRU: 2-layer GRU-variant, 512 sequential steps (reset gate dead).
// Persistent kernel, 128 CTAs x 512 threads (16 warps = 8 k-slices x 2 row
// halves). CTA i owns hidden cols [8i,8i+8): computes z & n, applies update.
// Packed fp32x2 FMA microkernel; double-buffered cp.async staging; ONE global
// barrier per timestep (skew-bounded correctness, see analysis in journal).
// ---------------------------------------------------------------------------

typedef unsigned long long ull;

#define BATCH 128
#define HID   1024
#define SEQ   512
#define INDIM 128
#define KC    64        // k-chunk size
#define KP    68        // inp smem row pitch (floats), 16B-aligned
#define NKW   8         // warps along k
#define NTHR  512

__device__ float    g_h0[2][BATCH][HID];
__device__ float    g_h1[2][BATCH][HID];
__device__ unsigned g_flags[128 * 32];   // one 128B-strided flag per CTA

struct SM {
    float inp[2][BATCH][KP];     // staged input chunk, double buffered
    float wgt[2][KC][16];        // staged W chunk: 8 z-cols then 8 n-cols
    float red[NKW][BATCH][18];   // cross-warp partial sums (pitch 18: no conflicts)
};

// ---------------- packed fp32x2 helpers ----------------
__device__ __forceinline__ ull rep2(float v) {
    ull r;
    asm("mov.b64 %0, {%1, %1};" : "=l"(r) : "f"(v));
    return r;
}
__device__ __forceinline__ void fma2(ull& d, ull a, ull b) {
    asm("fma.rn.f32x2 %0, %1, %2, %0;" : "+l"(d) : "l"(a), "l"(b));
}

// ---------------- cp.async helpers ----------------
__device__ __forceinline__ void cp16(void* dst, const void* src) {
    unsigned d = (unsigned)__cvta_generic_to_shared(dst);
    asm volatile("cp.async.cg.shared.global [%0], [%1], 16;" :: "r"(d), "l"(src));
}
__device__ __forceinline__ void cp_commit() { asm volatile("cp.async.commit_group;"); }
__device__ __forceinline__ void cp_wait0()  { asm volatile("cp.async.wait_group 0;"); }
__device__ __forceinline__ void cp_wait1()  { asm volatile("cp.async.wait_group 1;"); }

// ---------------- global barrier ----------------
__device__ __forceinline__ void gbar(unsigned& gen) {
    gen++;
    __syncthreads();
    if (threadIdx.x == 0) {
        asm volatile("st.release.gpu.global.u32 [%0], %1;"
                     :: "l"(&g_flags[blockIdx.x * 32]), "r"(gen) : "memory");
    }
    if (threadIdx.x < 128) {
        const unsigned* f = &g_flags[threadIdx.x * 32];
        unsigned v;
        while (true) {
            asm volatile("ld.acquire.gpu.global.u32 %0, [%1];" : "=r"(v) : "l"(f) : "memory");
            if (v >= gen) break;
            __nanosleep(32);
        }
    }
    __syncthreads();
}

// ---------------- chunk staging (512 threads) ----------------
__device__ __forceinline__ void stage_chunk(SM* s, int bb,
                                            const float* __restrict__ src, int rstride, int koff,
                                            const float* __restrict__ W, int kw0, int cb) {
    const int tid = threadIdx.x;
    // inp: 128 rows x 64 floats = 2048 float4 copies, 4 per thread
    #pragma unroll
    for (int it = 0; it < 4; it++) {
        int idx = it * NTHR + tid;
        int r = idx >> 4, q = idx & 15;
        cp16(&s->inp[bb][r][q * 4], src + (size_t)r * rstride + koff + q * 4);
    }
    // weights: 64 k x 16 cols (z cols cb..cb+7, n cols 2048+cb..+7)
    if (tid < 256) {
        int kk = tid >> 2, seg = tid & 3;
        int col = (seg < 2) ? (cb + seg * 4) : (2048 + cb + (seg - 2) * 4);
        cp16(&s->wgt[bb][kk][seg * 4], W + (size_t)(kw0 + kk) * 3072 + col);
    }
}

// ---------------- one GRU layer step for this CTA's 8 hidden cols -----------
__device__ __forceinline__ void run_layer(SM* s,
        const float* __restrict__ srcA, int strideA, int nA,
        const float* __restrict__ srcB, int strideB, int nB,
        const float* __restrict__ W, const float* __restrict__ bias,
        const float* __restrict__ hprev, float* __restrict__ hnext, int cb) {
    const int n    = nA + nB;
    const int tid  = threadIdx.x;
    const int warp = tid >> 5;
    const int kw   = warp >> 1;      // k-slice  0..7
    const int rh   = warp & 1;       // row half 0..1
    const int lane = tid & 31;
    const int rg   = lane & 15;
    const int ch   = lane >> 4;      // 0 -> z cols, 1 -> n cols
    const int rbase = rh * 64 + rg;  // rows rbase + 16*j, j=0..3

    ull acc[4][4];
    #pragma unroll
    for (int j = 0; j < 4; j++)
        #pragma unroll
        for (int cp = 0; cp < 4; cp++) acc[j][cp] = 0ull;

    stage_chunk(s, 0, srcA, strideA, 0, W, 0, cb);
    cp_commit();

    for (int c = 0; c < n; c++) {
        const int bb = c & 1;
        if (c + 1 < n) {
            const float* p; int st, ko;
            if (c + 1 < nA) { p = srcA; st = strideA; ko = (c + 1) * KC; }
            else            { p = srcB; st = strideB; ko = (c + 1 - nA) * KC; }
            stage_chunk(s, (c + 1) & 1, p, st, ko, W, (c + 1) * KC, cb);
            cp_commit();
            cp_wait1();
        } else {
            cp_wait0();
        }
        __syncthreads();

        #pragma unroll
        for (int kk = 0; kk < 8; kk++) {
            const int k = kw * 8 + kk;
            const ull* wr = (const ull*)&s->wgt[bb][k][ch * 8];
            ull w0 = wr[0], w1 = wr[1], w2 = wr[2], w3 = wr[3];
            #pragma unroll
            for (int j = 0; j < 4; j++) {
                ull iv = rep2(s->inp[bb][rbase + 16 * j][k]);
                fma2(acc[j][0], iv, w0);
                fma2(acc[j][1], iv, w1);
                fma2(acc[j][2], iv, w2);
                fma2(acc[j][3], iv, w3);
            }
        }
        __syncthreads();
    }

    // cross-warp partial dump (rh halves write disjoint rows of red[kw])
    #pragma unroll
    for (int j = 0; j < 4; j++)
        #pragma unroll
        for (int cp = 0; cp < 4; cp++)
            *(ull*)&s->red[kw][rbase + 16 * j][ch * 8 + 2 * cp] = acc[j][cp];
    __syncthreads();

    // reduce + activation + h update: 128 rows x 8 hcols = 1024 cells, 2/thread
    #pragma unroll
    for (int u0 = 0; u0 < 2; u0++) {
        int u   = u0 * NTHR + tid;
        int row = u & 127;
        int hco = u >> 7;            // 0..7
        float z  = bias[cb + hco];
        float nn = bias[2048 + cb + hco];
        #pragma unroll
        for (int ww = 0; ww < NKW; ww++) {
            z  += s->red[ww][row][hco];
            nn += s->red[ww][row][8 + hco];
        }
        z = 1.0f / (1.0f + __expf(-z));
        float e = __expf(2.0f * nn);             // tanh via exp
        nn = __fdividef(e - 1.0f, e + 1.0f);
        float hp = hprev[row * HID + cb + hco];
        hnext[row * HID + cb + hco] = (1.0f - z) * nn + z * hp;
    }
    __syncthreads();
}

// ---------------- persistent kernel ----------------
__global__ void __launch_bounds__(NTHR, 1)
gru_persistent(const float* __restrict__ x,
               const float* __restrict__ W0, const float* __restrict__ b0,
               const float* __restrict__ W1, const float* __restrict__ b1,
               const float* __restrict__ Wfc, const float* __restrict__ bfc,
               float* __restrict__ out) {
    extern __shared__ __align__(16) char sraw[];
    SM* s = (SM*)sraw;
    const int cb = blockIdx.x * 8;
    unsigned gen = 0;
    int p = 0;

    for (int t = 0; t < SEQ; t++) {
        const float* xt = x + (size_t)t * INDIM;
        // layer 0: inp = [x_t (128), h0 (1024)], K = 1152
        run_layer(s, xt, SEQ * INDIM, 2,
                     &g_h0[p][0][0], HID, 16,
                     W0, b0, &g_h0[p][0][0], &g_h0[p ^ 1][0][0], cb);
        gbar(gen);   // single barrier per step (skew analysis: sufficient)
        // layer 1: inp = [h0_new (1024), h1 (1024)], K = 2048
        run_layer(s, &g_h0[p ^ 1][0][0], HID, 16,
                     &g_h1[p][0][0], HID, 16,
                     W1, b1, &g_h1[p][0][0], &g_h1[p ^ 1][0][0], cb);
        p ^= 1;
    }
    gbar(gen);   // final: all h1 cols visible before FC

    // final FC: out[b] = h1_last[b,:] @ Wfc + bfc  (CTA b handles row b)
    const float* hf = &g_h1[p][0][0];
    const int row = blockIdx.x;
    float part = 0.0f;
    for (int j = threadIdx.x; j < HID; j += NTHR)
        part += hf[row * HID + j] * Wfc[j];
    float* rb = &s->red[0][0][0];
    rb[threadIdx.x] = part;
    __syncthreads();
    if (threadIdx.x == 0) {
        float tot = 0.0f;
        #pragma unroll 8
        for (int i = 0; i < NTHR; i++) tot += rb[i];
        out[row] = tot + bfc[0];
    }
}

// ---------------- per-launch state reset ----------------
__global__ void gru_init() {
    int i      = blockIdx.x * blockDim.x + threadIdx.x;
    int stride = gridDim.x * blockDim.x;
    for (int idx = i; idx < 2 * BATCH * HID; idx += stride) {
        ((float*)g_h0)[idx] = 0.0f;
        ((float*)g_h1)[idx] = 0.0f;
    }
    if (i < 128 * 32) g_flags[i] = 0u;
}

extern "C" void kernel_launch(void* const* d_in, const int* in_sizes, int n_in,
                              void* d_out, int out_size) {
    const float* x   = (const float*)d_in[0];
    const float* W0  = (const float*)d_in[1];
    const float* b0  = (const float*)d_in[2];
    const float* W1  = (const float*)d_in[3];
    const float* b1  = (const float*)d_in[4];
    const float* Wfc = (const float*)d_in[5];
    const float* bfc = (const float*)d_in[6];
    float* out = (float*)d_out;

    cudaFuncSetAttribute(gru_persistent,
                         cudaFuncAttributeMaxDynamicSharedMemorySize,
                         (int)sizeof(SM));
    gru_init<<<256, 256>>>();
    gru_persistent<<<128, NTHR, sizeof(SM)>>>(x, W0, b0, W1, b1, Wfc, bfc, out);
}

// round 5
// speedup vs baseline: 1.2715x; 1.0921x over previous
#include <cuda_runtime.h>
#include <cstdint>

// ---------------------------------------------------------------------------
// CustomSimpleGRU: 2-layer GRU-variant, 512 sequential steps (reset gate dead).
// Persistent kernel, 128 CTAs x 512 threads (16 warps = 8 k-slices x 2 row
// halves). CTA i owns hidden cols [8i,8i+8): computes z & n, applies update.
//
// R5 changes vs R4 (33.4ms):
//  * KP=130 (bank stride 2) + 8B cp.async  -> conflict-free iv broadcast LDS
//  * KC=128  -> 25 chunks/step (was 50): half the barriers/commits
//  * single __syncthreads per chunk (stage issued after the barrier)
// ---------------------------------------------------------------------------

typedef unsigned long long ull;

#define BATCH 128
#define HID   1024
#define SEQ   512
#define INDIM 128
#define KC    128       // k-chunk size
#define KP    130       // inp smem row pitch in floats: 130 % 32 == 2 -> no conflicts
#define NKW   8         // warps along k
#define NTHR  512

__device__ float    g_h0[2][BATCH][HID];
__device__ float    g_h1[2][BATCH][HID];
__device__ unsigned g_flags[128 * 32];   // one 128B-strided flag per CTA

struct SM {
    float inp[2][BATCH][KP];     // staged input chunk, double buffered (133.1KB)
    float wgt[2][KC][16];        // staged W chunk: 8 z-cols then 8 n-cols (16.4KB)
    float red[NKW][BATCH][18];   // cross-warp partial sums (73.7KB)
};                               // total ~223KB dynamic smem

// ---------------- packed fp32x2 helpers ----------------
__device__ __forceinline__ ull rep2(float v) {
    ull r;
    asm("mov.b64 %0, {%1, %1};" : "=l"(r) : "f"(v));
    return r;
}
__device__ __forceinline__ void fma2(ull& d, ull a, ull b) {
    asm("fma.rn.f32x2 %0, %1, %2, %0;" : "+l"(d) : "l"(a), "l"(b));
}

// ---------------- cp.async helpers ----------------
__device__ __forceinline__ void cp16(void* dst, const void* src) {
    unsigned d = (unsigned)__cvta_generic_to_shared(dst);
    asm volatile("cp.async.cg.shared.global [%0], [%1], 16;" :: "r"(d), "l"(src));
}
__device__ __forceinline__ void cp8(void* dst, const void* src) {
    unsigned d = (unsigned)__cvta_generic_to_shared(dst);
    asm volatile("cp.async.ca.shared.global [%0], [%1], 8;" :: "r"(d), "l"(src));
}
__device__ __forceinline__ void cp_commit() { asm volatile("cp.async.commit_group;"); }
__device__ __forceinline__ void cp_wait0()  { asm volatile("cp.async.wait_group 0;"); }

// ---------------- global barrier ----------------
__device__ __forceinline__ void gbar(unsigned& gen) {
    gen++;
    __syncthreads();
    if (threadIdx.x == 0) {
        asm volatile("st.release.gpu.global.u32 [%0], %1;"
                     :: "l"(&g_flags[blockIdx.x * 32]), "r"(gen) : "memory");
    }
    if (threadIdx.x < 128) {
        const unsigned* f = &g_flags[threadIdx.x * 32];
        unsigned v;
        while (true) {
            asm volatile("ld.acquire.gpu.global.u32 %0, [%1];" : "=r"(v) : "l"(f) : "memory");
            if (v >= gen) break;
            __nanosleep(32);
        }
    }
    __syncthreads();
}

// ---------------- chunk staging (512 threads, KC=128) ----------------
__device__ __forceinline__ void stage_chunk(SM* s, int bb,
                                            const float* __restrict__ src, int rstride, int koff,
                                            const float* __restrict__ W, int kw0, int cb) {
    const int tid = threadIdx.x;
    // inp: 128 rows x 128 floats = 8192 8-byte units, 16 per thread
    #pragma unroll
    for (int it = 0; it < 16; it++) {
        int idx = it * NTHR + tid;
        int r = idx >> 6, u = idx & 63;          // 64 x 8B units per row
        cp8(&s->inp[bb][r][u * 2], src + (size_t)r * rstride + koff + u * 2);
    }
    // weights: 128 k x 16 cols (z cols cb..cb+7, n cols 2048+cb..+7), 1 float4/thread
    {
        int kk = tid >> 2, seg = tid & 3;
        int col = (seg < 2) ? (cb + seg * 4) : (2048 + cb + (seg - 2) * 4);
        cp16(&s->wgt[bb][kk][seg * 4], W + (size_t)(kw0 + kk) * 3072 + col);
    }
}

// ---------------- one GRU layer step for this CTA's 8 hidden cols -----------
__device__ __forceinline__ void run_layer(SM* s,
        const float* __restrict__ srcA, int strideA, int nA,
        const float* __restrict__ srcB, int strideB, int nB,
        const float* __restrict__ W, const float* __restrict__ bias,
        const float* __restrict__ hprev, float* __restrict__ hnext, int cb) {
    const int n    = nA + nB;                 // chunks of KC
    const int tid  = threadIdx.x;
    const int warp = tid >> 5;
    const int kw   = warp >> 1;               // k-slice  0..7 (16 k each)
    const int rh   = warp & 1;                // row half 0..1
    const int lane = tid & 31;
    const int rg   = lane & 15;               // consecutive rows within a load
    const int ch   = lane >> 4;               // 0 -> z cols, 1 -> n cols
    const int rbase = rh * 64 + rg;           // rows rbase + 16*j, j=0..3

    ull acc[4][4];
    #pragma unroll
    for (int j = 0; j < 4; j++)
        #pragma unroll
        for (int cp = 0; cp < 4; cp++) acc[j][cp] = 0ull;

    stage_chunk(s, 0, srcA, strideA, 0, W, 0, cb);
    cp_commit();

    for (int c = 0; c < n; c++) {
        const int bb = c & 1;
        cp_wait0();          // stage(c) landed (only pending group)
        __syncthreads();     // visible to all; everyone done computing c-1
        if (c + 1 < n) {     // stage next AFTER barrier: buffer (c+1)&1 is free
            const float* p; int st, ko;
            if (c + 1 < nA) { p = srcA; st = strideA; ko = (c + 1) * KC; }
            else            { p = srcB; st = strideB; ko = (c + 1 - nA) * KC; }
            stage_chunk(s, (c + 1) & 1, p, st, ko, W, (c + 1) * KC, cb);
            cp_commit();
        }

        // compute chunk c: warp slice k in [kw*16, kw*16+16)
        #pragma unroll
        for (int kk = 0; kk < 16; kk++) {
            const int k = kw * 16 + kk;
            const ull* wr = (const ull*)&s->wgt[bb][k][ch * 8];
            ull w0 = wr[0], w1 = wr[1], w2 = wr[2], w3 = wr[3];
            #pragma unroll
            for (int j = 0; j < 4; j++) {
                ull iv = rep2(s->inp[bb][rbase + 16 * j][k]);
                fma2(acc[j][0], iv, w0);
                fma2(acc[j][1], iv, w1);
                fma2(acc[j][2], iv, w2);
                fma2(acc[j][3], iv, w3);
            }
        }
    }
    __syncthreads();   // all compute done before red writes race nothing; keep ordering

    // cross-warp partial dump (rh halves write disjoint rows of red[kw])
    #pragma unroll
    for (int j = 0; j < 4; j++)
        #pragma unroll
        for (int cp = 0; cp < 4; cp++)
            *(ull*)&s->red[kw][rbase + 16 * j][ch * 8 + 2 * cp] = acc[j][cp];
    __syncthreads();

    // reduce + activation + h update: 128 rows x 8 hcols = 1024 cells, 2/thread
    #pragma unroll
    for (int u0 = 0; u0 < 2; u0++) {
        int u   = u0 * NTHR + tid;
        int row = u & 127;
        int hco = u >> 7;            // 0..7
        float z  = bias[cb + hco];
        float nn = bias[2048 + cb + hco];
        #pragma unroll
        for (int ww = 0; ww < NKW; ww++) {
            z  += s->red[ww][row][hco];
            nn += s->red[ww][row][8 + hco];
        }
        z = 1.0f / (1.0f + __expf(-z));
        float e = __expf(2.0f * nn);             // tanh via exp
        nn = __fdividef(e - 1.0f, e + 1.0f);
        float hp = hprev[row * HID + cb + hco];
        hnext[row * HID + cb + hco] = (1.0f - z) * nn + z * hp;
    }
    __syncthreads();  // red free for next use
}

// ---------------- persistent kernel ----------------
__global__ void __launch_bounds__(NTHR, 1)
gru_persistent(const float* __restrict__ x,
               const float* __restrict__ W0, const float* __restrict__ b0,
               const float* __restrict__ W1, const float* __restrict__ b1,
               const float* __restrict__ Wfc, const float* __restrict__ bfc,
               float* __restrict__ out) {
    extern __shared__ __align__(16) char sraw[];
    SM* s = (SM*)sraw;
    const int cb = blockIdx.x * 8;
    unsigned gen = 0;
    int p = 0;

    for (int t = 0; t < SEQ; t++) {
        const float* xt = x + (size_t)t * INDIM;
        // layer 0: inp = [x_t (128 = 1 chunk), h0 (1024 = 8 chunks)], K = 1152
        run_layer(s, xt, SEQ * INDIM, 1,
                     &g_h0[p][0][0], HID, 8,
                     W0, b0, &g_h0[p][0][0], &g_h0[p ^ 1][0][0], cb);
        gbar(gen);   // single barrier per step (skew analysis: sufficient)
        // layer 1: inp = [h0_new (8 chunks), h1 (8 chunks)], K = 2048
        run_layer(s, &g_h0[p ^ 1][0][0], HID, 8,
                     &g_h1[p][0][0], HID, 8,
                     W1, b1, &g_h1[p][0][0], &g_h1[p ^ 1][0][0], cb);
        p ^= 1;
    }
    gbar(gen);   // final: all h1 cols visible before FC

    // final FC: out[b] = h1_last[b,:] @ Wfc + bfc  (CTA b handles row b)
    const float* hf = &g_h1[p][0][0];
    const int row = blockIdx.x;
    float part = 0.0f;
    for (int j = threadIdx.x; j < HID; j += NTHR)
        part += hf[row * HID + j] * Wfc[j];
    float* rb = &s->red[0][0][0];
    rb[threadIdx.x] = part;
    __syncthreads();
    if (threadIdx.x == 0) {
        float tot = 0.0f;
        #pragma unroll 8
        for (int i = 0; i < NTHR; i++) tot += rb[i];
        out[row] = tot + bfc[0];
    }
}

// ---------------- per-launch state reset ----------------
__global__ void gru_init() {
    int i      = blockIdx.x * blockDim.x + threadIdx.x;
    int stride = gridDim.x * blockDim.x;
    for (int idx = i; idx < 2 * BATCH * HID; idx += stride) {
        ((float*)g_h0)[idx] = 0.0f;
        ((float*)g_h1)[idx] = 0.0f;
    }
    if (i < 128 * 32) g_flags[i] = 0u;
}

extern "C" void kernel_launch(void* const* d_in, const int* in_sizes, int n_in,
                              void* d_out, int out_size) {
    const float* x   = (const float*)d_in[0];
    const float* W0  = (const float*)d_in[1];
    const float* b0  = (const float*)d_in[2];
    const float* W1  = (const float*)d_in[3];
    const float* b1  = (const float*)d_in[4];
    const float* Wfc = (const float*)d_in[5];
    const float* bfc = (const float*)d_in[6];
    float* out = (float*)d_out;

    cudaFuncSetAttribute(gru_persistent,
                         cudaFuncAttributeMaxDynamicSharedMemorySize,
                         (int)sizeof(SM));
    gru_init<<<256, 256>>>();
    gru_persistent<<<128, NTHR, sizeof(SM)>>>(x, W0, b0, W1, b1, Wfc, bfc, out);
}

// round 6
// speedup vs baseline: 1.2731x; 1.0013x over previous
#include <cuda_runtime.h>
#include <cstdint>

// ---------------------------------------------------------------------------
// CustomSimpleGRU: 2-layer GRU-variant, 512 sequential steps (reset gate dead).
// Persistent kernel, 128 CTAs x 512 threads (16 warps = 8 k-slices x 2 row
// halves). CTA i owns hidden cols [8i,8i+8): computes z & n, applies update.
//
// R5 changes vs R4 (33.4ms):
//  * KP=130 (bank stride 2) + 8B cp.async  -> conflict-free iv broadcast LDS
//  * KC=128  -> 25 chunks/step (was 50): half the barriers/commits
//  * single __syncthreads per chunk (stage issued after the barrier)
// ---------------------------------------------------------------------------

typedef unsigned long long ull;

#define BATCH 128
#define HID   1024
#define SEQ   512
#define INDIM 128
#define KC    128       // k-chunk size
#define KP    130       // inp smem row pitch in floats: 130 % 32 == 2 -> no conflicts
#define NKW   8         // warps along k
#define NTHR  512

__device__ float    g_h0[2][BATCH][HID];
__device__ float    g_h1[2][BATCH][HID];
__device__ unsigned g_flags[128 * 32];   // one 128B-strided flag per CTA

struct SM {
    float inp[2][BATCH][KP];     // staged input chunk, double buffered (133.1KB)
    float wgt[2][KC][16];        // staged W chunk: 8 z-cols then 8 n-cols (16.4KB)
    float red[NKW][BATCH][18];   // cross-warp partial sums (73.7KB)
};                               // total ~223KB dynamic smem

// ---------------- packed fp32x2 helpers ----------------
__device__ __forceinline__ ull rep2(float v) {
    ull r;
    asm("mov.b64 %0, {%1, %1};" : "=l"(r) : "f"(v));
    return r;
}
__device__ __forceinline__ void fma2(ull& d, ull a, ull b) {
    asm("fma.rn.f32x2 %0, %1, %2, %0;" : "+l"(d) : "l"(a), "l"(b));
}

// ---------------- cp.async helpers ----------------
__device__ __forceinline__ void cp16(void* dst, const void* src) {
    unsigned d = (unsigned)__cvta_generic_to_shared(dst);
    asm volatile("cp.async.cg.shared.global [%0], [%1], 16;" :: "r"(d), "l"(src));
}
__device__ __forceinline__ void cp8(void* dst, const void* src) {
    unsigned d = (unsigned)__cvta_generic_to_shared(dst);
    asm volatile("cp.async.ca.shared.global [%0], [%1], 8;" :: "r"(d), "l"(src));
}
__device__ __forceinline__ void cp_commit() { asm volatile("cp.async.commit_group;"); }
__device__ __forceinline__ void cp_wait0()  { asm volatile("cp.async.wait_group 0;"); }

// ---------------- global barrier ----------------
__device__ __forceinline__ void gbar(unsigned& gen) {
    gen++;
    __syncthreads();
    if (threadIdx.x == 0) {
        asm volatile("st.release.gpu.global.u32 [%0], %1;"
                     :: "l"(&g_flags[blockIdx.x * 32]), "r"(gen) : "memory");
    }
    if (threadIdx.x < 128) {
        const unsigned* f = &g_flags[threadIdx.x * 32];
        unsigned v;
        while (true) {
            asm volatile("ld.acquire.gpu.global.u32 %0, [%1];" : "=r"(v) : "l"(f) : "memory");
            if (v >= gen) break;
            __nanosleep(32);
        }
    }
    __syncthreads();
}

// ---------------- chunk staging (512 threads, KC=128) ----------------
__device__ __forceinline__ void stage_chunk(SM* s, int bb,
                                            const float* __restrict__ src, int rstride, int koff,
                                            const float* __restrict__ W, int kw0, int cb) {
    const int tid = threadIdx.x;
    // inp: 128 rows x 128 floats = 8192 8-byte units, 16 per thread
    #pragma unroll
    for (int it = 0; it < 16; it++) {
        int idx = it * NTHR + tid;
        int r = idx >> 6, u = idx & 63;          // 64 x 8B units per row
        cp8(&s->inp[bb][r][u * 2], src + (size_t)r * rstride + koff + u * 2);
    }
    // weights: 128 k x 16 cols (z cols cb..cb+7, n cols 2048+cb..+7), 1 float4/thread
    {
        int kk = tid >> 2, seg = tid & 3;
        int col = (seg < 2) ? (cb + seg * 4) : (2048 + cb + (seg - 2) * 4);
        cp16(&s->wgt[bb][kk][seg * 4], W + (size_t)(kw0 + kk) * 3072 + col);
    }
}

// ---------------- one GRU layer step for this CTA's 8 hidden cols -----------
__device__ __forceinline__ void run_layer(SM* s,
        const float* __restrict__ srcA, int strideA, int nA,
        const float* __restrict__ srcB, int strideB, int nB,
        const float* __restrict__ W, const float* __restrict__ bias,
        const float* __restrict__ hprev, float* __restrict__ hnext, int cb) {
    const int n    = nA + nB;                 // chunks of KC
    const int tid  = threadIdx.x;
    const int warp = tid >> 5;
    const int kw   = warp >> 1;               // k-slice  0..7 (16 k each)
    const int rh   = warp & 1;                // row half 0..1
    const int lane = tid & 31;
    const int rg   = lane & 15;               // consecutive rows within a load
    const int ch   = lane >> 4;               // 0 -> z cols, 1 -> n cols
    const int rbase = rh * 64 + rg;           // rows rbase + 16*j, j=0..3

    ull acc[4][4];
    #pragma unroll
    for (int j = 0; j < 4; j++)
        #pragma unroll
        for (int cp = 0; cp < 4; cp++) acc[j][cp] = 0ull;

    stage_chunk(s, 0, srcA, strideA, 0, W, 0, cb);
    cp_commit();

    for (int c = 0; c < n; c++) {
        const int bb = c & 1;
        cp_wait0();          // stage(c) landed (only pending group)
        __syncthreads();     // visible to all; everyone done computing c-1
        if (c + 1 < n) {     // stage next AFTER barrier: buffer (c+1)&1 is free
            const float* p; int st, ko;
            if (c + 1 < nA) { p = srcA; st = strideA; ko = (c + 1) * KC; }
            else            { p = srcB; st = strideB; ko = (c + 1 - nA) * KC; }
            stage_chunk(s, (c + 1) & 1, p, st, ko, W, (c + 1) * KC, cb);
            cp_commit();
        }

        // compute chunk c: warp slice k in [kw*16, kw*16+16)
        #pragma unroll
        for (int kk = 0; kk < 16; kk++) {
            const int k = kw * 16 + kk;
            const ull* wr = (const ull*)&s->wgt[bb][k][ch * 8];
            ull w0 = wr[0], w1 = wr[1], w2 = wr[2], w3 = wr[3];
            #pragma unroll
            for (int j = 0; j < 4; j++) {
                ull iv = rep2(s->inp[bb][rbase + 16 * j][k]);
                fma2(acc[j][0], iv, w0);
                fma2(acc[j][1], iv, w1);
                fma2(acc[j][2], iv, w2);
                fma2(acc[j][3], iv, w3);
            }
        }
    }
    __syncthreads();   // all compute done before red writes race nothing; keep ordering

    // cross-warp partial dump (rh halves write disjoint rows of red[kw])
    #pragma unroll
    for (int j = 0; j < 4; j++)
        #pragma unroll
        for (int cp = 0; cp < 4; cp++)
            *(ull*)&s->red[kw][rbase + 16 * j][ch * 8 + 2 * cp] = acc[j][cp];
    __syncthreads();

    // reduce + activation + h update: 128 rows x 8 hcols = 1024 cells, 2/thread
    #pragma unroll
    for (int u0 = 0; u0 < 2; u0++) {
        int u   = u0 * NTHR + tid;
        int row = u & 127;
        int hco = u >> 7;            // 0..7
        float z  = bias[cb + hco];
        float nn = bias[2048 + cb + hco];
        #pragma unroll
        for (int ww = 0; ww < NKW; ww++) {
            z  += s->red[ww][row][hco];
            nn += s->red[ww][row][8 + hco];
        }
        z = 1.0f / (1.0f + __expf(-z));
        float e = __expf(2.0f * nn);             // tanh via exp
        nn = __fdividef(e - 1.0f, e + 1.0f);
        float hp = hprev[row * HID + cb + hco];
        hnext[row * HID + cb + hco] = (1.0f - z) * nn + z * hp;
    }
    __syncthreads();  // red free for next use
}

// ---------------- persistent kernel ----------------
__global__ void __launch_bounds__(NTHR, 1)
gru_persistent(const float* __restrict__ x,
               const float* __restrict__ W0, const float* __restrict__ b0,
               const float* __restrict__ W1, const float* __restrict__ b1,
               const float* __restrict__ Wfc, const float* __restrict__ bfc,
               float* __restrict__ out) {
    extern __shared__ __align__(16) char sraw[];
    SM* s = (SM*)sraw;
    const int cb = blockIdx.x * 8;
    unsigned gen = 0;
    int p = 0;

    for (int t = 0; t < SEQ; t++) {
        const float* xt = x + (size_t)t * INDIM;
        // layer 0: inp = [x_t (128 = 1 chunk), h0 (1024 = 8 chunks)], K = 1152
        run_layer(s, xt, SEQ * INDIM, 1,
                     &g_h0[p][0][0], HID, 8,
                     W0, b0, &g_h0[p][0][0], &g_h0[p ^ 1][0][0], cb);
        gbar(gen);   // single barrier per step (skew analysis: sufficient)
        // layer 1: inp = [h0_new (8 chunks), h1 (8 chunks)], K = 2048
        run_layer(s, &g_h0[p ^ 1][0][0], HID, 8,
                     &g_h1[p][0][0], HID, 8,
                     W1, b1, &g_h1[p][0][0], &g_h1[p ^ 1][0][0], cb);
        p ^= 1;
    }
    gbar(gen);   // final: all h1 cols visible before FC

    // final FC: out[b] = h1_last[b,:] @ Wfc + bfc  (CTA b handles row b)
    const float* hf = &g_h1[p][0][0];
    const int row = blockIdx.x;
    float part = 0.0f;
    for (int j = threadIdx.x; j < HID; j += NTHR)
        part += hf[row * HID + j] * Wfc[j];
    float* rb = &s->red[0][0][0];
    rb[threadIdx.x] = part;
    __syncthreads();
    if (threadIdx.x == 0) {
        float tot = 0.0f;
        #pragma unroll 8
        for (int i = 0; i < NTHR; i++) tot += rb[i];
        out[row] = tot + bfc[0];
    }
}

// ---------------- per-launch state reset ----------------
__global__ void gru_init() {
    int i      = blockIdx.x * blockDim.x + threadIdx.x;
    int stride = gridDim.x * blockDim.x;
    for (int idx = i; idx < 2 * BATCH * HID; idx += stride) {
        ((float*)g_h0)[idx] = 0.0f;
        ((float*)g_h1)[idx] = 0.0f;
    }
    if (i < 128 * 32) g_flags[i] = 0u;
}

extern "C" void kernel_launch(void* const* d_in, const int* in_sizes, int n_in,
                              void* d_out, int out_size) {
    const float* x   = (const float*)d_in[0];
    const float* W0  = (const float*)d_in[1];
    const float* b0  = (const float*)d_in[2];
    const float* W1  = (const float*)d_in[3];
    const float* b1  = (const float*)d_in[4];
    const float* Wfc = (const float*)d_in[5];
    const float* bfc = (const float*)d_in[6];
    float* out = (float*)d_out;

    cudaFuncSetAttribute(gru_persistent,
                         cudaFuncAttributeMaxDynamicSharedMemorySize,
                         (int)sizeof(SM));
    gru_init<<<256, 256>>>();
    gru_persistent<<<128, NTHR, sizeof(SM)>>>(x, W0, b0, W1, b1, Wfc, bfc, out);
}

// round 9
// speedup vs baseline: 1.8006x; 1.4144x over previous
#include <cuda_runtime.h>
#include <cuda_bf16.h>
#include <cstdint>

typedef __nv_bfloat16 bf;
#define SEQ  512
#define NTHR 256
#define STG  24576
#define SMTOT (2*STG + 1280)
#define SW(o) ((o) ^ (((o) >> 3) & 0x70))

__device__ __align__(1024) bf g_xh[128][65536];
__device__ __align__(1024) bf g_xl[128][65536];
__device__ __align__(1024) bf g_w0h[2048][1152];
__device__ __align__(1024) bf g_w0l[2048][1152];
__device__ __align__(1024) bf g_w1h[2048][2048];
__device__ __align__(1024) bf g_w1l[2048][2048];
__device__ __align__(1024) bf g_hh[2][2][128][1024];  // [layer][ping][row][unit]
__device__ __align__(1024) bf g_hl[2][2][128][1024];
__device__ float    g_biasP[2][2048];
__device__ unsigned g_flags[128 * 32];

__device__ __forceinline__ uint32_t s2u(const void* p) {
    uint32_t a;
    asm("{ .reg .u64 t; cvta.to.shared.u64 t, %1; cvt.u32.u64 %0, t; }" : "=r"(a) : "l"(p));
    return a;
}
__device__ __forceinline__ void cp16(uint32_t dst, const void* src) {
    asm volatile("cp.async.cg.shared.global [%0], [%1], 16;" :: "r"(dst), "l"(src));
}
__device__ __forceinline__ void cpc() { asm volatile("cp.async.commit_group;"); }
__device__ __forceinline__ void cpw() { asm volatile("cp.async.wait_group 0;"); }
__device__ __forceinline__ void ldmx4(unsigned* r, uint32_t a) {
    asm volatile("ldmatrix.sync.aligned.m8n8.x4.shared.b16 {%0,%1,%2,%3}, [%4];"
        : "=r"(r[0]), "=r"(r[1]), "=r"(r[2]), "=r"(r[3]) : "r"(a));
}
__device__ __forceinline__ void mma(float* c, const unsigned* a, const unsigned* b) {
    asm volatile("mma.sync.aligned.m16n8k16.row.col.f32.bf16.bf16.f32 "
        "{%0,%1,%2,%3}, {%4,%5,%6,%7}, {%8,%9}, {%0,%1,%2,%3};"
        : "+f"(c[0]), "+f"(c[1]), "+f"(c[2]), "+f"(c[3])
        : "r"(a[0]), "r"(a[1]), "r"(a[2]), "r"(a[3]), "r"(b[0]), "r"(b[1]));
}
__device__ __forceinline__ void gbar(unsigned& gen) {
    gen++;
    __syncthreads();
    if (threadIdx.x == 0)
        asm volatile("st.release.gpu.global.u32 [%0], %1;"
                     :: "l"(&g_flags[blockIdx.x * 32]), "r"(gen) : "memory");
    if (threadIdx.x < 128) {
        const unsigned* f = &g_flags[threadIdx.x * 32];
        unsigned v;
        do {
            asm volatile("ld.acquire.gpu.global.u32 %0, [%1];" : "=r"(v) : "l"(f) : "memory");
            if (v < gen) __nanosleep(32);
        } while (v < gen);
    }
    __syncthreads();
}

__global__ void __launch_bounds__(NTHR, 1) gru_mma(
    const float* __restrict__ Wfc, const float* __restrict__ bfc,
    float* __restrict__ out) {
    extern __shared__ __align__(1024) char sm[];
    const uint32_t sb = s2u(sm);
    const int tid = threadIdx.x, warp = tid >> 5, lane = tid & 31;
    const int ctan = blockIdx.x & 63, ctam = blockIdx.x >> 6;
    float* sbias = (float*)(sm + 2 * STG);
    float* sred  = sbias + 64;
    if (tid < 64) sbias[tid] = g_biasP[tid >> 5][ctan * 32 + (tid & 31)];
    __syncthreads();

    const int wm = warp & 3, wn = warp >> 2;
    const uint32_t aoffA = (wm * 16 + (lane & 15)) * 128 + (lane >> 4) * 16;
    const uint32_t aoffB = (wn * 16 + ((lane >> 4) & 1) * 8 + (lane & 7)) * 128
                         + ((lane >> 3) & 1) * 16;
    unsigned gen = 0; int p = 0;

    auto layer = [&](int lay, int t) {
        const int n = lay ? 32 : 18;
        const bf* wh = lay ? &g_w1h[0][0] : &g_w0h[0][0];
        const bf* wl = lay ? &g_w1l[0][0] : &g_w0l[0][0];
        const long Kst = lay ? 2048 : 1152;

        auto stage = [&](int c, int bu) {
            const bf *ah, *al; long rstr; int ko;
            if (!lay) {
                if (c < 2) { ah = &g_xh[0][0]; al = &g_xl[0][0]; rstr = 65536; ko = t * 128 + c * 64; }
                else { ah = &g_hh[0][p][0][0]; al = &g_hl[0][p][0][0]; rstr = 1024; ko = (c - 2) * 64; }
            } else {
                if (c < 16) { ah = &g_hh[0][p ^ 1][0][0]; al = &g_hl[0][p ^ 1][0][0]; rstr = 1024; ko = c * 64; }
                else { ah = &g_hh[1][p][0][0]; al = &g_hl[1][p][0][0]; rstr = 1024; ko = (c - 16) * 64; }
            }
            uint32_t db = sb + bu * STG;
            #pragma unroll
            for (int it = 0; it < 4; it++) {
                int idx = it * NTHR + tid, d = idx >> 9, r = (idx >> 3) & 63, u = idx & 7;
                cp16(db + d * 8192 + SW(r * 128 + u * 16),
                     (d ? al : ah) + (long)(ctam * 64 + r) * rstr + ko + u * 8);
            }
            #pragma unroll
            for (int it = 0; it < 2; it++) {
                int idx = it * NTHR + tid, d = idx >> 8, r = (idx >> 3) & 31, u = idx & 7;
                cp16(db + 16384 + d * 4096 + SW(r * 128 + u * 16),
                     (d ? wl : wh) + (long)(ctan * 32 + r) * Kst + c * 64 + u * 8);
            }
            cpc();
        };

        float acc[2][4] = {{0, 0, 0, 0}, {0, 0, 0, 0}};
        stage(0, 0);
        for (int c = 0; c < n; c++) {
            const int bu = c & 1;
            cpw();
            __syncthreads();
            if (c + 1 < n) stage(c + 1, bu ^ 1);
            uint32_t tb = sb + bu * STG;
            #pragma unroll
            for (int kk = 0; kk < 4; kk++) {
                unsigned a4[4], l4[4], b4[4], m4[4];
                uint32_t oa = aoffA + kk * 32, ob = aoffB + kk * 32;
                ldmx4(a4, tb + SW(oa));
                ldmx4(l4, tb + 8192 + SW(oa));
                ldmx4(b4, tb + 16384 + SW(ob));
                ldmx4(m4, tb + 20480 + SW(ob));
                #pragma unroll
                for (int j = 0; j < 2; j++) {
                    mma(acc[j], a4, b4 + 2 * j);
                    mma(acc[j], a4, m4 + 2 * j);
                    mma(acc[j], l4, b4 + 2 * j);
                }
            }
        }
        __syncthreads();

        // epilogue: thread holds (z,n) of 2 units x 2 rows
        bf* hh = &g_hh[lay][p ^ 1][0][0];  bf* hl = &g_hl[lay][p ^ 1][0][0];
        const bf* qh = &g_hh[lay][p][0][0]; const bf* ql = &g_hl[lay][p][0][0];
        const int r0 = ctam * 64 + wm * 16 + (lane >> 2);
        #pragma unroll
        for (int j = 0; j < 2; j++) {
            int ul = wn * 8 + j * 4 + (lane & 3);
            int ug = ctan * 16 + ul;
            float bz = sbias[lay * 32 + 2 * ul], bn = sbias[lay * 32 + 2 * ul + 1];
            #pragma unroll
            for (int rr = 0; rr < 2; rr++) {
                int r = r0 + rr * 8;
                float z = 1.f / (1.f + __expf(-(acc[j][rr * 2] + bz)));
                float e = __expf(2.f * (acc[j][rr * 2 + 1] + bn));
                float nn = __fdividef(e - 1.f, e + 1.f);
                float hp = __bfloat162float(qh[r * 1024 + ug]) + __bfloat162float(ql[r * 1024 + ug]);
                float hv = (1.f - z) * nn + z * hp;
                bf hi = __float2bfloat16(hv);
                hh[r * 1024 + ug] = hi;
                hl[r * 1024 + ug] = __float2bfloat16(hv - __bfloat162float(hi));
            }
        }
        __syncthreads();
    };

    for (int t = 0; t < SEQ; t++) {
        layer(0, t);
        gbar(gen);
        layer(1, t);
        p ^= 1;
    }
    gbar(gen);

    // final FC: CTA b -> out[b]
    const bf* fh = &g_hh[1][p][0][0];
    const bf* fl = &g_hl[1][p][0][0];
    const int row = blockIdx.x;
    float part = 0.f;
    for (int j = tid; j < 1024; j += NTHR)
        part += (__bfloat162float(fh[row * 1024 + j]) + __bfloat162float(fl[row * 1024 + j])) * Wfc[j];
    sred[tid] = part;
    __syncthreads();
    if (tid == 0) {
        float s = 0.f;
        #pragma unroll 8
        for (int i = 0; i < NTHR; i++) s += sred[i];
        out[row] = s + bfc[0];
    }
}

__global__ void ginit(const float* __restrict__ x,
                      const float* __restrict__ b0, const float* __restrict__ b1) {
    long i = (long)blockIdx.x * blockDim.x + threadIdx.x;
    long st = (long)gridDim.x * blockDim.x;
    for (long idx = i; idx < 128L * 65536; idx += st) {
        float v = x[idx];
        bf h = __float2bfloat16(v);
        ((bf*)g_xh)[idx] = h;
        ((bf*)g_xl)[idx] = __float2bfloat16(v - __bfloat162float(h));
    }
    bf z = __float2bfloat16(0.f);
    for (long idx = i; idx < 2L * 2 * 128 * 1024; idx += st) {
        ((bf*)g_hh)[idx] = z; ((bf*)g_hl)[idx] = z;
    }
    if (i < 128 * 32) g_flags[i] = 0u;
    if (i < 4096) {
        int l = (int)(i >> 11), g = (int)(i & 2047);
        int u = g >> 1, col = (g & 1) ? 2048 + u : u;
        g_biasP[l][g] = l ? b1[col] : b0[col];
    }
}

__global__ void prepw(const float* __restrict__ W0, const float* __restrict__ W1) {
    const int l = blockIdx.z;
    const float* W = l ? W1 : W0;
    bf* Dh = l ? &g_w1h[0][0] : &g_w0h[0][0];
    bf* Dl = l ? &g_w1l[0][0] : &g_w0l[0][0];
    const int K = l ? 2048 : 1152;
    const int k0 = blockIdx.x * 32; if (k0 >= K) return;
    const int g0 = blockIdx.y * 32;
    __shared__ float tile[32][33];
    const int tx = threadIdx.x, ty = threadIdx.y;
    {
        int g = g0 + tx, u = g >> 1, col = (g & 1) ? 2048 + u : u;
        #pragma unroll
        for (int r = 0; r < 32; r += 8)
            tile[ty + r][tx] = W[(size_t)(k0 + ty + r) * 3072 + col];
    }
    __syncthreads();
    #pragma unroll
    for (int r = 0; r < 32; r += 8) {
        float v = tile[tx][ty + r];
        bf h = __float2bfloat16(v);
        size_t o = (size_t)(g0 + ty + r) * K + k0 + tx;
        Dh[o] = h;
        Dl[o] = __float2bfloat16(v - __bfloat162float(h));
    }
}

extern "C" void kernel_launch(void* const* d_in, const int* in_sizes, int n_in,
                              void* d_out, int out_size) {
    const float* x   = (const float*)d_in[0];
    const float* W0  = (const float*)d_in[1];
    const float* b0  = (const float*)d_in[2];
    const float* W1  = (const float*)d_in[3];
    const float* b1  = (const float*)d_in[4];
    const float* Wfc = (const float*)d_in[5];
    const float* bfc = (const float*)d_in[6];
    float* out = (float*)d_out;

    cudaFuncSetAttribute(gru_mma, cudaFuncAttributeMaxDynamicSharedMemorySize, SMTOT);
    ginit<<<2048, 256>>>(x, b0, b1);
    prepw<<<dim3(64, 64, 2), dim3(32, 8)>>>(W0, W1);
    gru_mma<<<128, NTHR, SMTOT>>>(Wfc, bfc, out);
}

// round 10
// speedup vs baseline: 2.6845x; 1.4909x over previous
#include <cuda_runtime.h>
#include <cuda_bf16.h>
#include <cstdint>

typedef __nv_bfloat16 bf;
#define SEQ  512
#define NTHR 256
#define STG  24576
#define SMTOT (4*STG + 1280)
#define SW(o) ((o) ^ (((o) >> 3) & 0x70))

__device__ __align__(1024) bf g_xh[128][65536];
__device__ __align__(1024) bf g_xl[128][65536];
__device__ __align__(1024) bf g_w0h[2048][1152];
__device__ __align__(1024) bf g_w0l[2048][1152];
__device__ __align__(1024) bf g_w1h[2048][2048];
__device__ __align__(1024) bf g_w1l[2048][2048];
__device__ __align__(1024) bf g_hh[2][2][128][1024];  // [layer][ping][row][unit]
__device__ __align__(1024) bf g_hl[2][2][128][1024];
__device__ float    g_biasP[2][2048];
__device__ unsigned g_flags[128 * 32];

__device__ __forceinline__ uint32_t s2u(const void* p) {
    uint32_t a;
    asm("{ .reg .u64 t; cvta.to.shared.u64 t, %1; cvt.u32.u64 %0, t; }" : "=r"(a) : "l"(p));
    return a;
}
__device__ __forceinline__ void cp16(uint32_t dst, const void* src) {
    asm volatile("cp.async.cg.shared.global [%0], [%1], 16;" :: "r"(dst), "l"(src));
}
__device__ __forceinline__ void cpc() { asm volatile("cp.async.commit_group;"); }
__device__ __forceinline__ void cpw_n(int n) {
    if (n <= 0)      asm volatile("cp.async.wait_group 0;");
    else if (n == 1) asm volatile("cp.async.wait_group 1;");
    else             asm volatile("cp.async.wait_group 2;");
}
__device__ __forceinline__ void ldmx4(unsigned* r, uint32_t a) {
    asm volatile("ldmatrix.sync.aligned.m8n8.x4.shared.b16 {%0,%1,%2,%3}, [%4];"
        : "=r"(r[0]), "=r"(r[1]), "=r"(r[2]), "=r"(r[3]) : "r"(a));
}
__device__ __forceinline__ void mma(float* c, const unsigned* a, const unsigned* b) {
    asm volatile("mma.sync.aligned.m16n8k16.row.col.f32.bf16.bf16.f32 "
        "{%0,%1,%2,%3}, {%4,%5,%6,%7}, {%8,%9}, {%0,%1,%2,%3};"
        : "+f"(c[0]), "+f"(c[1]), "+f"(c[2]), "+f"(c[3])
        : "r"(a[0]), "r"(a[1]), "r"(a[2]), "r"(a[3]), "r"(b[0]), "r"(b[1]));
}
__device__ __forceinline__ void gbar(unsigned& gen) {
    gen++;
    __syncthreads();
    if (threadIdx.x == 0)
        asm volatile("st.release.gpu.global.u32 [%0], %1;"
                     :: "l"(&g_flags[blockIdx.x * 32]), "r"(gen) : "memory");
    if (threadIdx.x < 128) {
        const unsigned* f = &g_flags[threadIdx.x * 32];
        unsigned v;
        do {
            asm volatile("ld.acquire.gpu.global.u32 %0, [%1];" : "=r"(v) : "l"(f) : "memory");
            if (v < gen) __nanosleep(32);
        } while (v < gen);
    }
    __syncthreads();
}

__global__ void __launch_bounds__(NTHR, 1) gru_mma(
    const float* __restrict__ Wfc, const float* __restrict__ bfc,
    float* __restrict__ out) {
    extern __shared__ __align__(1024) char sm[];
    const uint32_t sb = s2u(sm);
    const int tid = threadIdx.x, warp = tid >> 5, lane = tid & 31;
    const int ctan = blockIdx.x & 63, ctam = blockIdx.x >> 6;
    float* sbias = (float*)(sm + 4 * STG);
    float* sred  = sbias + 64;
    if (tid < 64) sbias[tid] = g_biasP[tid >> 5][ctan * 32 + (tid & 31)];
    __syncthreads();

    const int wm = warp & 3, wn = warp >> 2;
    const uint32_t aoffA = (wm * 16 + (lane & 15)) * 128 + (lane >> 4) * 16;
    const uint32_t aoffB = (wn * 16 + ((lane >> 4) & 1) * 8 + (lane & 7)) * 128
                         + ((lane >> 3) & 1) * 16;
    unsigned gen = 0; int p = 0;
    int pcnt = 0, ccnt = 0;           // producer / consumer chunk counters
    float acc[2][4];

    // stage chunk c of (lay, tt, ping=pp) into buffer pcnt&3
    auto stageF = [&](int lay, int tt, int pp, int c) {
        const bf *ah, *al; long rstr; int ko;
        if (!lay) {
            if (c < 2) { ah = &g_xh[0][0]; al = &g_xl[0][0]; rstr = 65536; ko = tt * 128 + c * 64; }
            else { ah = &g_hh[0][pp][0][0]; al = &g_hl[0][pp][0][0]; rstr = 1024; ko = (c - 2) * 64; }
        } else {
            if (c < 16) { ah = &g_hh[0][pp ^ 1][0][0]; al = &g_hl[0][pp ^ 1][0][0]; rstr = 1024; ko = c * 64; }
            else { ah = &g_hh[1][pp][0][0]; al = &g_hl[1][pp][0][0]; rstr = 1024; ko = (c - 16) * 64; }
        }
        const bf* wh = lay ? &g_w1h[0][0] : &g_w0h[0][0];
        const bf* wl = lay ? &g_w1l[0][0] : &g_w0l[0][0];
        const long Kst = lay ? 2048 : 1152;
        uint32_t db = sb + (pcnt & 3) * STG;
        #pragma unroll
        for (int it = 0; it < 4; it++) {
            int idx = it * NTHR + tid, d = idx >> 9, r = (idx >> 3) & 63, u = idx & 7;
            cp16(db + d * 8192 + SW(r * 128 + u * 16),
                 (d ? al : ah) + (long)(ctam * 64 + r) * rstr + ko + u * 8);
        }
        #pragma unroll
        for (int it = 0; it < 2; it++) {
            int idx = it * NTHR + tid, d = idx >> 8, r = (idx >> 3) & 31, u = idx & 7;
            cp16(db + 16384 + d * 4096 + SW(r * 128 + u * 16),
                 (d ? wl : wh) + (long)(ctan * 32 + r) * Kst + c * 64 + u * 8);
        }
        cpc(); pcnt++;
    };

    auto computeC = [&]() {
        uint32_t tb = sb + (ccnt & 3) * STG;
        #pragma unroll
        for (int kk = 0; kk < 4; kk++) {
            unsigned a4[4], l4[4], b4[4], m4[4];
            uint32_t oa = aoffA + kk * 32, ob = aoffB + kk * 32;
            ldmx4(a4, tb + SW(oa));
            ldmx4(l4, tb + 8192 + SW(oa));
            ldmx4(b4, tb + 16384 + SW(ob));
            ldmx4(m4, tb + 20480 + SW(ob));
            #pragma unroll
            for (int j = 0; j < 2; j++) {
                mma(acc[j], a4, b4 + 2 * j);
                mma(acc[j], a4, m4 + 2 * j);
                mma(acc[j], l4, b4 + 2 * j);
            }
        }
        ccnt++;
    };

    auto epi = [&](int lay) {
        __syncthreads();
        bf* hh = &g_hh[lay][p ^ 1][0][0];  bf* hl = &g_hl[lay][p ^ 1][0][0];
        const bf* qh = &g_hh[lay][p][0][0]; const bf* ql = &g_hl[lay][p][0][0];
        const int r0 = ctam * 64 + wm * 16 + (lane >> 2);
        #pragma unroll
        for (int j = 0; j < 2; j++) {
            int ul = wn * 8 + j * 4 + (lane & 3);
            int ug = ctan * 16 + ul;
            float bz = sbias[lay * 32 + 2 * ul], bn = sbias[lay * 32 + 2 * ul + 1];
            #pragma unroll
            for (int rr = 0; rr < 2; rr++) {
                int r = r0 + rr * 8;
                float z = 1.f / (1.f + __expf(-(acc[j][rr * 2] + bz)));
                float e = __expf(2.f * (acc[j][rr * 2 + 1] + bn));
                float nn = __fdividef(e - 1.f, e + 1.f);
                float hp = __bfloat162float(qh[r * 1024 + ug]) + __bfloat162float(ql[r * 1024 + ug]);
                float hv = (1.f - z) * nn + z * hp;
                bf hi = __float2bfloat16(hv);
                hh[r * 1024 + ug] = hi;
                hl[r * 1024 + ug] = __float2bfloat16(hv - __bfloat162float(hi));
            }
        }
        __syncthreads();
    };

    // initial fill for layer0(t=0)
    stageF(0, 0, 0, 0); stageF(0, 0, 0, 1); stageF(0, 0, 0, 2);

    for (int t = 0; t < SEQ; t++) {
        // ---- layer 0: 18 chunks ----
        acc[0][0]=acc[0][1]=acc[0][2]=acc[0][3]=0.f;
        acc[1][0]=acc[1][1]=acc[1][2]=acc[1][3]=0.f;
        for (int c = 0; c < 18; c++) {
            cpw_n(pcnt - ccnt - 1);
            __syncthreads();
            if (c + 3 < 18) stageF(0, t, p, c + 3);
            computeC();
        }
        epi(0);
        gbar(gen);
        // ---- layer 1: 32 chunks (fill after gbar) ----
        stageF(1, t, p, 0); stageF(1, t, p, 1); stageF(1, t, p, 2);
        acc[0][0]=acc[0][1]=acc[0][2]=acc[0][3]=0.f;
        acc[1][0]=acc[1][1]=acc[1][2]=acc[1][3]=0.f;
        for (int c = 0; c < 32; c++) {
            cpw_n(pcnt - ccnt - 1);
            __syncthreads();
            if (c + 3 < 32) stageF(1, t, p, c + 3);
            else if (t + 1 < SEQ) stageF(0, t + 1, p ^ 1, c + 3 - 32);  // prefetch next layer0
            computeC();
        }
        epi(1);
        p ^= 1;
    }
    gbar(gen);

    // final FC: CTA b -> out[b]
    const bf* fh = &g_hh[1][p][0][0];
    const bf* fl = &g_hl[1][p][0][0];
    const int row = blockIdx.x;
    float part = 0.f;
    for (int j = tid; j < 1024; j += NTHR)
        part += (__bfloat162float(fh[row * 1024 + j]) + __bfloat162float(fl[row * 1024 + j])) * Wfc[j];
    sred[tid] = part;
    __syncthreads();
    if (tid == 0) {
        float s = 0.f;
        #pragma unroll 8
        for (int i = 0; i < NTHR; i++) s += sred[i];
        out[row] = s + bfc[0];
    }
}

__global__ void ginit(const float* __restrict__ x,
                      const float* __restrict__ b0, const float* __restrict__ b1) {
    long i = (long)blockIdx.x * blockDim.x + threadIdx.x;
    long st = (long)gridDim.x * blockDim.x;
    for (long idx = i; idx < 128L * 65536; idx += st) {
        float v = x[idx];
        bf h = __float2bfloat16(v);
        ((bf*)g_xh)[idx] = h;
        ((bf*)g_xl)[idx] = __float2bfloat16(v - __bfloat162float(h));
    }
    bf z = __float2bfloat16(0.f);
    for (long idx = i; idx < 2L * 2 * 128 * 1024; idx += st) {
        ((bf*)g_hh)[idx] = z; ((bf*)g_hl)[idx] = z;
    }
    if (i < 128 * 32) g_flags[i] = 0u;
    if (i < 4096) {
        int l = (int)(i >> 11), g = (int)(i & 2047);
        int u = g >> 1, col = (g & 1) ? 2048 + u : u;
        g_biasP[l][g] = l ? b1[col] : b0[col];
    }
}

__global__ void prepw(const float* __restrict__ W0, const float* __restrict__ W1) {
    const int l = blockIdx.z;
    const float* W = l ? W1 : W0;
    bf* Dh = l ? &g_w1h[0][0] : &g_w0h[0][0];
    bf* Dl = l ? &g_w1l[0][0] : &g_w0l[0][0];
    const int K = l ? 2048 : 1152;
    const int k0 = blockIdx.x * 32; if (k0 >= K) return;
    const int g0 = blockIdx.y * 32;
    __shared__ float tile[32][33];
    const int tx = threadIdx.x, ty = threadIdx.y;
    {
        int g = g0 + tx, u = g >> 1, col = (g & 1) ? 2048 + u : u;
        #pragma unroll
        for (int r = 0; r < 32; r += 8)
            tile[ty + r][tx] = W[(size_t)(k0 + ty + r) * 3072 + col];
    }
    __syncthreads();
    #pragma unroll
    for (int r = 0; r < 32; r += 8) {
        float v = tile[tx][ty + r];
        bf h = __float2bfloat16(v);
        size_t o = (size_t)(g0 + ty + r) * K + k0 + tx;
        Dh[o] = h;
        Dl[o] = __float2bfloat16(v - __bfloat162float(h));
    }
}

extern "C" void kernel_launch(void* const* d_in, const int* in_sizes, int n_in,
                              void* d_out, int out_size) {
    const float* x   = (const float*)d_in[0];
    const float* W0  = (const float*)d_in[1];
    const float* b0  = (const float*)d_in[2];
    const float* W1  = (const float*)d_in[3];
    const float* b1  = (const float*)d_in[4];
    const float* Wfc = (const float*)d_in[5];
    const float* bfc = (const float*)d_in[6];
    float* out = (float*)d_out;

    cudaFuncSetAttribute(gru_mma, cudaFuncAttributeMaxDynamicSharedMemorySize, SMTOT);
    ginit<<<2048, 256>>>(x, b0, b1);
    prepw<<<dim3(64, 64, 2), dim3(32, 8)>>>(W0, W1);
    gru_mma<<<128, NTHR, SMTOT>>>(Wfc, bfc, out);
}